// round 1
// baseline (speedup 1.0000x reference)
#include <cuda_runtime.h>
#include <math.h>

// Problem constants
#define Bn  2
#define Ln  2048
#define Dn  1024
#define Hn  16
#define DHn 64
#define BHn (Bn*Hn)   // 32
#define Mrows (Bn*Ln) // 4096

// Scratch: q/k/v in [bh][l][dh] layout (fp32). 3 x 16 MB static device arrays.
__device__ float g_q[(size_t)BHn*Ln*DHn];
__device__ float g_k[(size_t)BHn*Ln*DHn];
__device__ float g_v[(size_t)BHn*Ln*DHn];

// ---------------------------------------------------------------------------
// Fused QKV projection: y = x @ W^T + b, written directly as [b,h,l,dh].
// Tile: 64(M) x 64(N), K-chunk 16. 256 threads, 4x4 microtile per thread.
// Smem tiles stored K-outer (transposed) so inner loop is 2 LDS.128 + 16 FFMA.
// ---------------------------------------------------------------------------
__global__ __launch_bounds__(256) void qkv_gemm(
    const float* __restrict__ x,
    const float* __restrict__ Wq, const float* __restrict__ bq,
    const float* __restrict__ Wk, const float* __restrict__ bk,
    const float* __restrict__ Wv, const float* __restrict__ bv)
{
    __shared__ float As[16][64];   // As[k][row]
    __shared__ float Bs[16][64];   // Bs[k][col]

    const float* W; const float* bias; float* dst;
    if (blockIdx.z == 0)      { W = Wq; bias = bq; dst = g_q; }
    else if (blockIdx.z == 1) { W = Wk; bias = bk; dst = g_k; }
    else                      { W = Wv; bias = bv; dst = g_v; }

    const int tid = threadIdx.x;
    const int tx = tid & 15;        // 0..15 -> col group
    const int ty = tid >> 4;        // 0..15 -> row group
    const int rowBase = blockIdx.y * 64;
    const int colBase = blockIdx.x * 64;

    // loader mapping: 256 threads, each reads one float4 of A and one of B per chunk
    const int lr = tid >> 2;        // 0..63  (tile row / tile col)
    const int lk = tid & 3;         // 0..3   (k-quad)

    float acc[4][4];
    #pragma unroll
    for (int r = 0; r < 4; r++)
        #pragma unroll
        for (int c = 0; c < 4; c++) acc[r][c] = 0.f;

    for (int kb = 0; kb < Dn; kb += 16) {
        float4 av = *(const float4*)&x[(size_t)(rowBase + lr) * Dn + kb + lk * 4];
        float4 wv = *(const float4*)&W[(size_t)(colBase + lr) * Dn + kb + lk * 4];
        __syncthreads();   // previous chunk's compute done before overwrite
        As[lk*4+0][lr] = av.x; As[lk*4+1][lr] = av.y;
        As[lk*4+2][lr] = av.z; As[lk*4+3][lr] = av.w;
        Bs[lk*4+0][lr] = wv.x; Bs[lk*4+1][lr] = wv.y;
        Bs[lk*4+2][lr] = wv.z; Bs[lk*4+3][lr] = wv.w;
        __syncthreads();

        #pragma unroll
        for (int k = 0; k < 16; k++) {
            float4 a = *(const float4*)&As[k][ty * 4];
            float4 b = *(const float4*)&Bs[k][tx * 4];
            acc[0][0] += a.x*b.x; acc[0][1] += a.x*b.y; acc[0][2] += a.x*b.z; acc[0][3] += a.x*b.w;
            acc[1][0] += a.y*b.x; acc[1][1] += a.y*b.y; acc[1][2] += a.y*b.z; acc[1][3] += a.y*b.w;
            acc[2][0] += a.z*b.x; acc[2][1] += a.z*b.y; acc[2][2] += a.z*b.z; acc[2][3] += a.z*b.w;
            acc[3][0] += a.w*b.x; acc[3][1] += a.w*b.y; acc[3][2] += a.w*b.z; acc[3][3] += a.w*b.w;
        }
    }

    // store with head relayout: col tile (64 wide) == exactly one head
    const int h = colBase >> 6;          // DH = 64
    float4 bb = *(const float4*)&bias[colBase + tx * 4];
    #pragma unroll
    for (int r = 0; r < 4; r++) {
        int gr = rowBase + ty * 4 + r;   // global row in [0, 4096)
        int b  = gr >> 11;               // / 2048
        int l  = gr & (Ln - 1);
        float4 o;
        o.x = acc[r][0] + bb.x;
        o.y = acc[r][1] + bb.y;
        o.z = acc[r][2] + bb.z;
        o.w = acc[r][3] + bb.w;
        *(float4*)&dst[((size_t)(b * Hn + h) * Ln + l) * DHn + tx * 4] = o;
    }
}

// ---------------------------------------------------------------------------
// Flash attention (causal), fp32. One thread = one query row.
// Block: 128 threads = 128 query rows of one (b,h). Keys streamed in BN=32 tiles.
// Online softmax in exp2 domain; 1/sqrt(DH) and log2(e) folded into q.
// ---------------------------------------------------------------------------
#define BM 128
#define BN 32

__global__ __launch_bounds__(128) void attn_kernel(float* __restrict__ out)
{
    __shared__ float Ks[BN][DHn];   // 8 KB
    __shared__ float Vs[BN][DHn];   // 8 KB

    const int bh  = blockIdx.y;
    const int qt  = blockIdx.x;
    const int tid = threadIdx.x;
    const int qrow = qt * BM + tid;

    // load q row into registers, pre-scaled by (1/8) * log2(e)
    const float scale = 0.125f * 1.4426950408889634f;
    const float4* qp = (const float4*)&g_q[((size_t)bh * Ln + qrow) * DHn];
    float4 q4[16];
    #pragma unroll
    for (int t = 0; t < 16; t++) {
        float4 v = qp[t];
        q4[t].x = v.x * scale; q4[t].y = v.y * scale;
        q4[t].z = v.z * scale; q4[t].w = v.w * scale;
    }

    float4 acc4[16];
    #pragma unroll
    for (int t = 0; t < 16; t++) acc4[t] = make_float4(0.f, 0.f, 0.f, 0.f);
    float m = -INFINITY, lsum = 0.f;

    const int ktiles = (qt + 1) * (BM / BN);
    const float4* kg_base = (const float4*)&g_k[(size_t)bh * Ln * DHn];
    const float4* vg_base = (const float4*)&g_v[(size_t)bh * Ln * DHn];

    for (int kt = 0; kt < ktiles; kt++) {
        __syncthreads();
        // cooperative tile load: 512 float4 each, 128 threads x 4
        float4* ks4 = (float4*)&Ks[0][0];
        float4* vs4 = (float4*)&Vs[0][0];
        const float4* kg = kg_base + (size_t)kt * BN * (DHn / 4);
        const float4* vg = vg_base + (size_t)kt * BN * (DHn / 4);
        #pragma unroll
        for (int i = 0; i < 4; i++) {
            ks4[i * 128 + tid] = kg[i * 128 + tid];
            vs4[i * 128 + tid] = vg[i * 128 + tid];
        }
        __syncthreads();

        const int rel = qrow - kt * BN;   // valid keys: j <= rel
        if (rel >= 0) {
            float s[BN];
            float mtile = m;
            #pragma unroll
            for (int j = 0; j < BN; j++) {
                const float4* kr = (const float4*)&Ks[j][0];
                float d0 = 0.f, d1 = 0.f, d2 = 0.f, d3 = 0.f;
                #pragma unroll
                for (int t = 0; t < 16; t += 4) {
                    float4 k0 = kr[t], k1 = kr[t+1], k2 = kr[t+2], k3 = kr[t+3];
                    d0 += q4[t  ].x*k0.x + q4[t  ].y*k0.y + q4[t  ].z*k0.z + q4[t  ].w*k0.w;
                    d1 += q4[t+1].x*k1.x + q4[t+1].y*k1.y + q4[t+1].z*k1.z + q4[t+1].w*k1.w;
                    d2 += q4[t+2].x*k2.x + q4[t+2].y*k2.y + q4[t+2].z*k2.z + q4[t+2].w*k2.w;
                    d3 += q4[t+3].x*k3.x + q4[t+3].y*k3.y + q4[t+3].z*k3.z + q4[t+3].w*k3.w;
                }
                float d = (d0 + d1) + (d2 + d3);
                if (j > rel) d = -1e30f;          // causal mask
                s[j] = d;
                mtile = fmaxf(mtile, d);
            }
            float corr = exp2f(m - mtile);        // m = -inf first time -> 0
            m = mtile;
            lsum *= corr;
            #pragma unroll
            for (int t = 0; t < 16; t++) {
                acc4[t].x *= corr; acc4[t].y *= corr;
                acc4[t].z *= corr; acc4[t].w *= corr;
            }
            #pragma unroll
            for (int j = 0; j < BN; j++) {
                float p = exp2f(s[j] - mtile);
                lsum += p;
                const float4* vr = (const float4*)&Vs[j][0];
                #pragma unroll
                for (int t = 0; t < 16; t++) {
                    float4 v = vr[t];
                    acc4[t].x += p * v.x; acc4[t].y += p * v.y;
                    acc4[t].z += p * v.z; acc4[t].w += p * v.w;
                }
            }
        }
    }

    const float inv = 1.0f / lsum;
    const int b = bh >> 4, h = bh & (Hn - 1);
    float4* op = (float4*)&out[((size_t)(b * Ln + qrow)) * Dn + h * DHn];
    #pragma unroll
    for (int t = 0; t < 16; t++) {
        float4 o;
        o.x = acc4[t].x * inv; o.y = acc4[t].y * inv;
        o.z = acc4[t].z * inv; o.w = acc4[t].w * inv;
        op[t] = o;
    }
}

// ---------------------------------------------------------------------------
// Launch. Inputs (metadata order): x, atten_mask, Wq, bq, Wk, bk, Wv, bv.
// atten_mask is the strict upper-triangular causal mask -> handled analytically.
// ---------------------------------------------------------------------------
extern "C" void kernel_launch(void* const* d_in, const int* in_sizes, int n_in,
                              void* d_out, int out_size)
{
    (void)in_sizes; (void)n_in; (void)out_size;
    const float* x  = (const float*)d_in[0];
    const float* Wq = (const float*)d_in[2];
    const float* bq = (const float*)d_in[3];
    const float* Wk = (const float*)d_in[4];
    const float* bk = (const float*)d_in[5];
    const float* Wv = (const float*)d_in[6];
    const float* bv = (const float*)d_in[7];
    float* out = (float*)d_out;

    qkv_gemm<<<dim3(Dn / 64, Mrows / 64, 3), 256>>>(x, Wq, bq, Wk, bk, Wv, bv);
    attn_kernel<<<dim3(Ln / BM, BHn), BM>>>(out);
}

// round 4
// speedup vs baseline: 3.8609x; 3.8609x over previous
#include <cuda_runtime.h>
#include <math.h>
#include <stdint.h>

// Problem constants
#define Bn  2
#define Ln  2048
#define Dn  1024
#define Hn  16
#define DHn 64
#define BHn (Bn*Hn)   // 32
#define Mrows (Bn*Ln) // 4096

// Scratch: q/k/v in [bh][l][dh] layout (fp32).
__device__ float g_q[(size_t)BHn*Ln*DHn];
__device__ float g_k[(size_t)BHn*Ln*DHn];
__device__ float g_v[(size_t)BHn*Ln*DHn];

// ---------------------------------------------------------------------------
// tf32 helpers
// ---------------------------------------------------------------------------
__device__ __forceinline__ uint32_t f2tf32(float x) {
    uint32_t r;
    asm("cvt.rna.tf32.f32 %0, %1;" : "=r"(r) : "f"(x));
    return r;
}

// D += A(16x8,row) * B(8x8,col), tf32 inputs, fp32 accum
__device__ __forceinline__ void mma_tf32(float d[4], const uint32_t a[4], const uint32_t b[2]) {
    asm volatile(
        "mma.sync.aligned.m16n8k8.row.col.f32.tf32.tf32.f32 "
        "{%0,%1,%2,%3}, {%4,%5,%6,%7}, {%8,%9}, {%0,%1,%2,%3};\n"
        : "+f"(d[0]), "+f"(d[1]), "+f"(d[2]), "+f"(d[3])
        : "r"(a[0]), "r"(a[1]), "r"(a[2]), "r"(a[3]),
          "r"(b[0]), "r"(b[1]));
}

// ---------------------------------------------------------------------------
// QKV projection: y = x @ W^T + b, written as [b,h,l,dh].
// Block tile 128(M) x 128(N), BK=16. 256 threads = 8 warps (2m x 4n),
// warp tile 64x32 = 4x4 m16n8k8 fragments. Smem holds tf32 bits, [row][k]+pad.
// ---------------------------------------------------------------------------
#define GBK 16

__global__ __launch_bounds__(256) void qkv_gemm_tf32(
    const float* __restrict__ x,
    const float* __restrict__ Wq, const float* __restrict__ bq,
    const float* __restrict__ Wk, const float* __restrict__ bk,
    const float* __restrict__ Wv, const float* __restrict__ bv)
{
    __shared__ uint32_t As[128][GBK + 4];
    __shared__ uint32_t Bs[128][GBK + 4];

    const float* W; const float* bias; float* dst;
    if (blockIdx.z == 0)      { W = Wq; bias = bq; dst = g_q; }
    else if (blockIdx.z == 1) { W = Wk; bias = bk; dst = g_k; }
    else                      { W = Wv; bias = bv; dst = g_v; }

    const int tid  = threadIdx.x;
    const int lane = tid & 31;
    const int warp = tid >> 5;
    const int wm   = warp >> 2;      // 0..1
    const int wn   = warp & 3;       // 0..3
    const int rowBase = blockIdx.y * 128;
    const int colBase = blockIdx.x * 128;

    // loaders: thread -> (row, k-half): 8 floats = 2 float4 per buffer
    const int ldRow = tid >> 1;          // 0..127
    const int ldK   = (tid & 1) * 8;     // 0 or 8

    float acc[4][4][4];
    #pragma unroll
    for (int mt = 0; mt < 4; mt++)
        #pragma unroll
        for (int nt = 0; nt < 4; nt++)
            #pragma unroll
            for (int i = 0; i < 4; i++) acc[mt][nt][i] = 0.f;

    const float* aptr = x + (size_t)(rowBase + ldRow) * Dn + ldK;
    const float* bptr = W + (size_t)(colBase + ldRow) * Dn + ldK;

    for (int kb = 0; kb < Dn; kb += GBK) {
        float4 av0 = *(const float4*)(aptr + kb);
        float4 av1 = *(const float4*)(aptr + kb + 4);
        float4 bv0 = *(const float4*)(bptr + kb);
        float4 bv1 = *(const float4*)(bptr + kb + 4);
        __syncthreads();  // previous chunk compute done
        {
            uint4 u0 = { f2tf32(av0.x), f2tf32(av0.y), f2tf32(av0.z), f2tf32(av0.w) };
            uint4 u1 = { f2tf32(av1.x), f2tf32(av1.y), f2tf32(av1.z), f2tf32(av1.w) };
            *(uint4*)&As[ldRow][ldK]     = u0;
            *(uint4*)&As[ldRow][ldK + 4] = u1;
            uint4 w0 = { f2tf32(bv0.x), f2tf32(bv0.y), f2tf32(bv0.z), f2tf32(bv0.w) };
            uint4 w1 = { f2tf32(bv1.x), f2tf32(bv1.y), f2tf32(bv1.z), f2tf32(bv1.w) };
            *(uint4*)&Bs[ldRow][ldK]     = w0;
            *(uint4*)&Bs[ldRow][ldK + 4] = w1;
        }
        __syncthreads();

        #pragma unroll
        for (int kc = 0; kc < 2; kc++) {
            const int c = kc * 8 + (lane & 3);
            uint32_t af[4][4];
            #pragma unroll
            for (int mt = 0; mt < 4; mt++) {
                int r = wm * 64 + mt * 16 + (lane >> 2);
                af[mt][0] = As[r][c];
                af[mt][1] = As[r + 8][c];
                af[mt][2] = As[r][c + 4];
                af[mt][3] = As[r + 8][c + 4];
            }
            uint32_t bf[4][2];
            #pragma unroll
            for (int nt = 0; nt < 4; nt++) {
                int n = wn * 32 + nt * 8 + (lane >> 2);
                bf[nt][0] = Bs[n][c];
                bf[nt][1] = Bs[n][c + 4];
            }
            #pragma unroll
            for (int mt = 0; mt < 4; mt++)
                #pragma unroll
                for (int nt = 0; nt < 4; nt++)
                    mma_tf32(acc[mt][nt], af[mt], bf[nt]);
        }
    }

    // epilogue: bias + head relayout into [bh][l][dh]
    #pragma unroll
    for (int nt = 0; nt < 4; nt++) {
        int gcol = colBase + wn * 32 + nt * 8 + 2 * (lane & 3);
        int h  = gcol >> 6;
        int dh = gcol & (DHn - 1);
        float bb0 = bias[gcol], bb1 = bias[gcol + 1];
        #pragma unroll
        for (int mt = 0; mt < 4; mt++) {
            int grow = rowBase + wm * 64 + mt * 16 + (lane >> 2);
            {
                int b = grow >> 11, l = grow & (Ln - 1);
                float2 v = { acc[mt][nt][0] + bb0, acc[mt][nt][1] + bb1 };
                *(float2*)&dst[((size_t)(b * Hn + h) * Ln + l) * DHn + dh] = v;
            }
            {
                int grow2 = grow + 8;
                int b = grow2 >> 11, l = grow2 & (Ln - 1);
                float2 v = { acc[mt][nt][2] + bb0, acc[mt][nt][3] + bb1 };
                *(float2*)&dst[((size_t)(b * Hn + h) * Ln + l) * DHn + dh] = v;
            }
        }
    }
}

// ---------------------------------------------------------------------------
// Flash attention (causal) with tf32 MMA.
// Block: 128 threads = 4 warps; 64 q rows per block (16 per warp).
// Key/value tiles of 32. S = Q@K^T and O += P@V via m16n8k8, online softmax
// on C-fragments. P round-trips through warp-private smem rows.
// ---------------------------------------------------------------------------
__global__ __launch_bounds__(128) void attn_tf32(float* __restrict__ out)
{
    __shared__ uint32_t QP[64][68];  // Q staging (tf32), then P (tf32)
    __shared__ uint32_t Ks[32][68];  // tf32 bits [key][dh]
    __shared__ uint32_t Vs[32][72];  // tf32 bits [key][dh]

    const int bh   = blockIdx.y;
    const int qt   = blockIdx.x;
    const int qbase = qt * 64;
    const int tid  = threadIdx.x;
    const int lane = tid & 31;
    const int warp = tid >> 5;

    const float qscale = 0.125f * 1.4426950408889634f;  // (1/sqrt64)*log2(e)

    // ---- stage Q (prescaled, tf32) ----
    {
        const float* qg = g_q + ((size_t)bh * Ln + qbase) * DHn;
        #pragma unroll
        for (int i = 0; i < 8; i++) {
            int idx = i * 128 + tid;          // 1024 float4
            int row = idx >> 4, c4 = idx & 15;
            float4 v = *(const float4*)(qg + (size_t)row * DHn + c4 * 4);
            uint4 u = { f2tf32(v.x * qscale), f2tf32(v.y * qscale),
                        f2tf32(v.z * qscale), f2tf32(v.w * qscale) };
            *(uint4*)&QP[row][c4 * 4] = u;
        }
    }
    __syncthreads();

    // ---- build Q fragments (held in regs for the whole kernel) ----
    const int r0 = warp * 16 + (lane >> 2);
    uint32_t qf[8][4];
    #pragma unroll
    for (int kc = 0; kc < 8; kc++) {
        int c = kc * 8 + (lane & 3);
        qf[kc][0] = QP[r0][c];
        qf[kc][1] = QP[r0 + 8][c];
        qf[kc][2] = QP[r0][c + 4];
        qf[kc][3] = QP[r0 + 8][c + 4];
    }

    float m0 = -1e30f, m1 = -1e30f, l0 = 0.f, l1 = 0.f;
    float oacc[8][4];
    #pragma unroll
    for (int nt = 0; nt < 8; nt++)
        #pragma unroll
        for (int i = 0; i < 4; i++) oacc[nt][i] = 0.f;

    const float* kg = g_k + (size_t)bh * Ln * DHn;
    const float* vg = g_v + (size_t)bh * Ln * DHn;
    const int grow0 = qbase + warp * 16 + (lane >> 2);
    const int grow1 = grow0 + 8;

    const int nkt = 2 * qt + 2;
    for (int kt = 0; kt < nkt; kt++) {
        __syncthreads();   // previous tile's reads complete
        // ---- load K/V tile (32x64 each) ----
        #pragma unroll
        for (int i = 0; i < 4; i++) {
            int idx = i * 128 + tid;          // 512 float4 per buffer
            int row = idx >> 4, c4 = idx & 15;
            size_t g = ((size_t)(kt * 32 + row)) * DHn + c4 * 4;
            float4 kv = *(const float4*)(kg + g);
            float4 vv = *(const float4*)(vg + g);
            uint4 uk = { f2tf32(kv.x), f2tf32(kv.y), f2tf32(kv.z), f2tf32(kv.w) };
            uint4 uv = { f2tf32(vv.x), f2tf32(vv.y), f2tf32(vv.z), f2tf32(vv.w) };
            *(uint4*)&Ks[row][c4 * 4] = uk;
            *(uint4*)&Vs[row][c4 * 4] = uv;
        }
        __syncthreads();

        // ---- S = Q @ K^T  (16 q-rows x 32 keys per warp) ----
        float sacc[4][4];
        #pragma unroll
        for (int nt = 0; nt < 4; nt++)
            #pragma unroll
            for (int i = 0; i < 4; i++) sacc[nt][i] = 0.f;

        #pragma unroll
        for (int kc = 0; kc < 8; kc++) {
            const int c = kc * 8 + (lane & 3);
            uint32_t kf[4][2];
            #pragma unroll
            for (int nt = 0; nt < 4; nt++) {
                int n = nt * 8 + (lane >> 2);
                kf[nt][0] = Ks[n][c];
                kf[nt][1] = Ks[n][c + 4];
            }
            #pragma unroll
            for (int nt = 0; nt < 4; nt++)
                mma_tf32(sacc[nt], qf[kc], kf[nt]);
        }

        // ---- causal mask (only near the diagonal) ----
        if (kt * 32 + 31 > qbase + warp * 16) {
            #pragma unroll
            for (int nt = 0; nt < 4; nt++) {
                int gc0 = kt * 32 + nt * 8 + 2 * (lane & 3);
                int gc1 = gc0 + 1;
                if (gc0 > grow0) sacc[nt][0] = -1e30f;
                if (gc1 > grow0) sacc[nt][1] = -1e30f;
                if (gc0 > grow1) sacc[nt][2] = -1e30f;
                if (gc1 > grow1) sacc[nt][3] = -1e30f;
            }
        }

        // ---- online softmax: row max over the 4-lane row group ----
        float tm0 = -1e30f, tm1 = -1e30f;
        #pragma unroll
        for (int nt = 0; nt < 4; nt++) {
            tm0 = fmaxf(tm0, fmaxf(sacc[nt][0], sacc[nt][1]));
            tm1 = fmaxf(tm1, fmaxf(sacc[nt][2], sacc[nt][3]));
        }
        tm0 = fmaxf(tm0, __shfl_xor_sync(0xffffffff, tm0, 1));
        tm0 = fmaxf(tm0, __shfl_xor_sync(0xffffffff, tm0, 2));
        tm1 = fmaxf(tm1, __shfl_xor_sync(0xffffffff, tm1, 1));
        tm1 = fmaxf(tm1, __shfl_xor_sync(0xffffffff, tm1, 2));

        float mn0 = fmaxf(m0, tm0), mn1 = fmaxf(m1, tm1);
        float sc0 = exp2f(m0 - mn0), sc1 = exp2f(m1 - mn1);
        m0 = mn0; m1 = mn1;
        l0 *= sc0; l1 *= sc1;
        #pragma unroll
        for (int nt = 0; nt < 8; nt++) {
            oacc[nt][0] *= sc0; oacc[nt][1] *= sc0;
            oacc[nt][2] *= sc1; oacc[nt][3] *= sc1;
        }

        // ---- p = exp2(s - m), tf32-rounded; write to warp-private P rows ----
        #pragma unroll
        for (int nt = 0; nt < 4; nt++) {
            int col = nt * 8 + 2 * (lane & 3);
            uint32_t u00 = f2tf32(exp2f(sacc[nt][0] - mn0));
            uint32_t u01 = f2tf32(exp2f(sacc[nt][1] - mn0));
            uint32_t u10 = f2tf32(exp2f(sacc[nt][2] - mn1));
            uint32_t u11 = f2tf32(exp2f(sacc[nt][3] - mn1));
            l0 += __uint_as_float(u00) + __uint_as_float(u01);
            l1 += __uint_as_float(u10) + __uint_as_float(u11);
            uint2 p0 = { u00, u01 };
            uint2 p1 = { u10, u11 };
            *(uint2*)&QP[r0][col]     = p0;
            *(uint2*)&QP[r0 + 8][col] = p1;
        }
        __syncwarp();

        // ---- O += P @ V ----
        #pragma unroll
        for (int kc = 0; kc < 4; kc++) {
            const int c = kc * 8 + (lane & 3);
            uint32_t pf[4];
            pf[0] = QP[r0][c];
            pf[1] = QP[r0 + 8][c];
            pf[2] = QP[r0][c + 4];
            pf[3] = QP[r0 + 8][c + 4];
            #pragma unroll
            for (int nt = 0; nt < 8; nt++) {
                uint32_t vf[2];
                int n = nt * 8 + (lane >> 2);
                vf[0] = Vs[c & 7][n];        // key = kc*8 + (lane&3)
                vf[1] = Vs[(c & 7) + 4][n];
                // note: c&7 == (lane&3) when kc*8 masked out; fix below
                vf[0] = Vs[kc * 8 + (lane & 3)][n];
                vf[1] = Vs[kc * 8 + (lane & 3) + 4][n];
                mma_tf32(oacc[nt], pf, vf);
            }
        }
        // (next iteration's __syncthreads protects P and K/V reuse)
    }

    // ---- epilogue ----
    l0 += __shfl_xor_sync(0xffffffff, l0, 1);
    l0 += __shfl_xor_sync(0xffffffff, l0, 2);
    l1 += __shfl_xor_sync(0xffffffff, l1, 1);
    l1 += __shfl_xor_sync(0xffffffff, l1, 2);
    float inv0 = 1.f / l0, inv1 = 1.f / l1;

    const int b = bh >> 4, h = bh & (Hn - 1);
    float* o0 = out + ((size_t)(b * Ln + grow0)) * Dn + h * DHn;
    float* o1 = out + ((size_t)(b * Ln + grow1)) * Dn + h * DHn;
    #pragma unroll
    for (int nt = 0; nt < 8; nt++) {
        int dh = nt * 8 + 2 * (lane & 3);
        float2 v0 = { oacc[nt][0] * inv0, oacc[nt][1] * inv0 };
        float2 v1 = { oacc[nt][2] * inv1, oacc[nt][3] * inv1 };
        *(float2*)(o0 + dh) = v0;
        *(float2*)(o1 + dh) = v1;
    }
}

// ---------------------------------------------------------------------------
// Launch. Inputs: x, atten_mask, Wq, bq, Wk, bk, Wv, bv. Mask is strict
// upper-triangular causal -> handled analytically.
// ---------------------------------------------------------------------------
extern "C" void kernel_launch(void* const* d_in, const int* in_sizes, int n_in,
                              void* d_out, int out_size)
{
    (void)in_sizes; (void)n_in; (void)out_size;
    const float* x  = (const float*)d_in[0];
    const float* Wq = (const float*)d_in[2];
    const float* bq = (const float*)d_in[3];
    const float* Wk = (const float*)d_in[4];
    const float* bk = (const float*)d_in[5];
    const float* Wv = (const float*)d_in[6];
    const float* bv = (const float*)d_in[7];
    float* out = (float*)d_out;

    qkv_gemm_tf32<<<dim3(Dn / 128, Mrows / 128, 3), 256>>>(x, Wq, bq, Wk, bk, Wv, bv);
    attn_tf32<<<dim3(Ln / 64, BHn), 128>>>(out);
}